// round 15
// baseline (speedup 1.0000x reference)
#include <cuda_runtime.h>
#include <cuda_bf16.h>
#include <stdint.h>

// ---------------- problem constants ----------------
#define BB     4
#define CCH    256          // FIN
#define SS     4096         // H*W
#define MP     (BB*SS)      // 16384 positions
#define NMEM   64
#define SQG    16
#define QKROWS 2048         // 1024 q rows + 1024 k rows
#define CINR   258          // FIN + 2 pos channels
#define KPAD   288          // CINR padded: 4x64 + 1x32 k-tiles
#define NKT    5
#define NQBLK  1024         // number of q-blocks in merged GEMM

// ---------------- scratch (device globals; no allocation) ----------------
__device__ __nv_bfloat16 g_A[(size_t)MP * KPAD];          // xp^T bf16, K padded
__device__ __nv_bfloat16 g_W[(size_t)QKROWS * KPAD];      // [wq; wk] bf16, K padded
__device__ float         g_qsum[(size_t)MP * SQG];        // sum over slots of normalized q
__device__ unsigned      g_qcnt;                          // q-block completion counter
__device__ float         g_attn[(size_t)MP * NMEM];       // attn_mean per position
__device__ float         g_Wv[NMEM * CCH];                // v @ wout^T (fused tail)

// ---------------- PTX helpers (base sm_103 only) ----------------
__device__ __forceinline__ uint32_t smem_u32(const void* p) {
    uint32_t a;
    asm("{ .reg .u64 t; cvta.to.shared.u64 t, %1; cvt.u32.u64 %0, t; }" : "=r"(a) : "l"(p));
    return a;
}
__device__ __forceinline__ void cp16(uint32_t saddr, const void* g) {
    asm volatile("cp.async.cg.shared.global [%0], [%1], 16;\n" :: "r"(saddr), "l"(g));
}
__device__ __forceinline__ void cp_commit() {
    asm volatile("cp.async.commit_group;\n" ::: "memory");
}
template <int N> __device__ __forceinline__ void cp_wait() {
    asm volatile("cp.async.wait_group %0;\n" :: "n"(N) : "memory");
}
__device__ __forceinline__ void mma16816(float* c, const unsigned* a, const unsigned* b) {
    asm volatile(
        "mma.sync.aligned.m16n8k16.row.col.f32.bf16.bf16.f32 "
        "{%0,%1,%2,%3}, {%4,%5,%6,%7}, {%8,%9}, {%0,%1,%2,%3};\n"
        : "+f"(c[0]), "+f"(c[1]), "+f"(c[2]), "+f"(c[3])
        : "r"(a[0]), "r"(a[1]), "r"(a[2]), "r"(a[3]), "r"(b[0]), "r"(b[1]));
}
__device__ __forceinline__ void ldsm_x4(unsigned& r0, unsigned& r1, unsigned& r2,
                                        unsigned& r3, uint32_t a) {
    asm volatile("ldmatrix.sync.aligned.m8n8.x4.shared.b16 {%0,%1,%2,%3}, [%4];"
                 : "=r"(r0), "=r"(r1), "=r"(r2), "=r"(r3) : "r"(a));
}
// SW128 swizzle for 128-byte rows
__device__ __forceinline__ uint32_t swz(uint32_t off) { return off ^ ((off >> 3) & 0x70); }

// ---------------- prep: transpose x into g_A (cols 0..255), vectorized ----------------
__global__ __launch_bounds__(256) void prep_x_kernel(const float* __restrict__ x) {
    __shared__ float tile[32][33];
    int b  = blockIdx.z;
    int c0 = blockIdx.x * 32;
    int s0 = blockIdx.y * 32;
    int t  = threadIdx.x;
    {   // load 32c x 32s with float4 in s
        int row = t >> 3, col = (t & 7) * 4;
        float4 vv = *reinterpret_cast<const float4*>(
            &x[((size_t)b * CCH + c0 + row) * SS + s0 + col]);
        tile[row][col]     = vv.x; tile[row][col + 1] = vv.y;
        tile[row][col + 2] = vv.z; tile[row][col + 3] = vv.w;
    }
    __syncthreads();
    {   // write: one p-row, 4 consecutive c as 8B store
        int si = t >> 3, c4 = (t & 7) * 4;
        int p = b * SS + s0 + si;
        __nv_bfloat16 h[4];
#pragma unroll
        for (int j = 0; j < 4; j++) h[j] = __float2bfloat16(tile[c4 + j][si]);
        *reinterpret_cast<uint2*>(&g_A[(size_t)p * KPAD + c0 + c4]) =
            *reinterpret_cast<uint2*>(h);
    }
}

// ---------------- prep: pos channels + zero pad (cols 256..287) ----------------
__global__ void prep_pos_kernel(const float* __restrict__ pos) {
    int g = blockIdx.x * blockDim.x + threadIdx.x;   // MP*32 threads
    int p = g >> 5, cc = g & 31;
    int s = p & (SS - 1);
    float v = 0.f;
    if (cc == 0)      v = pos[s];
    else if (cc == 1) v = pos[SS + s];
    g_A[(size_t)p * KPAD + 256 + cc] = __float2bfloat16(v);
}

// ---------------- prep: weights [wq; wk] -> bf16 padded ----------------
__global__ void prep_w_kernel(const float* __restrict__ wq, const float* __restrict__ wk) {
    int g = blockIdx.x * blockDim.x + threadIdx.x;   // QKROWS*KPAD threads
    int r = g / KPAD, c = g % KPAD;
    float v = 0.f;
    if (c < CINR) v = (r < 1024) ? wq[r * CINR + c] : wk[(r - 1024) * CINR + c];
    g_W[g] = __float2bfloat16(v);
}

// ---------------- prep: Wv[m][o] = sum_f v[m][f] * wout[o][f] ----------------
// grid (NMEM, 16); block 256 = 16 o-lanes x 16 f-segments; short chains, no atomics.
__global__ __launch_bounds__(256) void prep_wv_kernel(const float* __restrict__ v,
                                                      const float* __restrict__ wout) {
    __shared__ float vs[CCH];
    __shared__ float part[256];
    int m  = blockIdx.x;
    int oc = blockIdx.y;          // chunk of 16 outputs
    int tid = threadIdx.x;
    int ol = tid & 15, fs = tid >> 4;
    vs[tid] = v[m * CCH + tid];
    __syncthreads();
    int o = oc * 16 + ol;
    const float4* wr = reinterpret_cast<const float4*>(wout + (size_t)o * CCH + fs * 16);
    float acc = 0.f;
#pragma unroll
    for (int i = 0; i < 4; i++) {
        float4 w = wr[i];
        int f = fs * 16 + i * 4;
        acc += vs[f] * w.x + vs[f + 1] * w.y + vs[f + 2] * w.z + vs[f + 3] * w.w;
    }
    part[fs * 16 + ol] = acc;
    __syncthreads();
    if (tid < 16) {
        float s = 0.f;
#pragma unroll
        for (int k2 = 0; k2 < 16; k2++) s += part[k2 * 16 + tid];
        g_Wv[m * CCH + oc * 16 + tid] = s;
    }
}

// ---------------- merged fused GEMM + normalization (single launch) ----------------
// grid (128, 16): blockIdx.y < 8 -> q rows, >= 8 -> k rows. q-blocks flush g_qsum
// then bump g_qcnt; k-blocks spin on g_qcnt AFTER their MMA main loop, then emit attn.
#define GBM 128
#define GBN 128
#define STAGE_A   16384
#define SM_AOFF(s) ((s) * STAGE_A)
#define SM_BOFF(s) (32768 + (s) * STAGE_A)
#define QS_OFF    65536                 // 128 x 17 x 4 = 8704
#define BIAS_OFF  74240                 // 128 x 4 = 512 (block-local slots)
#define SM_TOTAL  74752
#define QSP       17

__device__ __forceinline__ void stage_tile(uint32_t sbase, uint32_t aoff, uint32_t boff,
                                           int m0, int n0, int kt, int tid) {
    int kk = kt * 64;
    if (kt < 4) {
#pragma unroll
        for (int i = 0; i < 4; i++) {
            int idx = tid + i * 256;
            int row = idx >> 3, ch = idx & 7;
            uint32_t so = swz(row * 128 + ch * 16);
            cp16(sbase + aoff + so, &g_A[(size_t)(m0 + row) * KPAD + kk + ch * 8]);
            cp16(sbase + boff + so, &g_W[(size_t)(n0 + row) * KPAD + kk + ch * 8]);
        }
    } else {
#pragma unroll
        for (int i = 0; i < 2; i++) {
            int idx = tid + i * 256;
            int row = idx >> 2, ch = idx & 3;
            uint32_t so = swz(row * 128 + ch * 16);
            cp16(sbase + aoff + so, &g_A[(size_t)(m0 + row) * KPAD + kk + ch * 8]);
            cp16(sbase + boff + so, &g_W[(size_t)(n0 + row) * KPAD + kk + ch * 8]);
        }
    }
    cp_commit();
}

__global__ __launch_bounds__(256, 2) void gemm_qk_kernel(const float* __restrict__ bq,
                                                         const float* __restrict__ bk) {
    extern __shared__ __align__(1024) char smem[];
    uint32_t sbase = smem_u32(smem);
    float* qs_s   = reinterpret_cast<float*>(smem + QS_OFF);
    float* bias_s = reinterpret_cast<float*>(smem + BIAS_OFF);
    int tid  = threadIdx.x;
    int warp = tid >> 5, lane = tid & 31;
    int wm = warp & 1, wn = warp >> 1;      // warp grid 2(m) x 4(n)
    int gr = lane >> 2, tg = lane & 3;
    int by = blockIdx.y;
    int isK = (by >= 8);
    int m0 = blockIdx.x * GBM;
    int n0 = by * GBN;                      // contiguous [q;k] rows of g_W
    const float* bias = isK ? bk : bq;
    int slot0 = (by & 7) * 8;               // first slot handled by this block

    // ldmatrix lane geometry
    int j  = lane >> 3;
    int jm = j & 1;
    uint32_t kadd = (uint32_t)(j >> 1) * 16;
    uint32_t xorv = (uint32_t)(lane & 7) << 4;
    int rA[4], rB[2];
#pragma unroll
    for (int mf = 0; mf < 4; mf++) rA[mf] = wm * 64 + mf * 16 + jm * 8 + (lane & 7);
#pragma unroll
    for (int nh = 0; nh < 2; nh++) rB[nh] = wn * 32 + nh * 16 + jm * 8 + (lane & 7);

    float acc[4][4][4];
#pragma unroll
    for (int i = 0; i < 4; i++)
#pragma unroll
        for (int jj = 0; jj < 4; jj++)
#pragma unroll
            for (int q = 0; q < 4; q++) acc[i][jj][q] = 0.f;

    // prologue: stage tile 0; zero qs smem; load this block's 128 bias values
    stage_tile(sbase, SM_AOFF(0), SM_BOFF(0), m0, n0, 0, tid);
    for (int i = tid; i < GBM * QSP; i += 256) qs_s[i] = 0.f;
    if (tid < 128) bias_s[tid] = bias[slot0 * 16 + tid];

    for (int kt = 0; kt < NKT; kt++) {
        uint32_t aoff = SM_AOFF(kt & 1);
        uint32_t boff = SM_BOFF(kt & 1);
        if (kt + 1 < NKT) {
            stage_tile(sbase, SM_AOFF((kt + 1) & 1), SM_BOFF((kt + 1) & 1),
                       m0, n0, kt + 1, tid);
            cp_wait<1>();
        } else {
            cp_wait<0>();
        }
        __syncthreads();

        uint32_t abase[4], bbase[2];
#pragma unroll
        for (int mf = 0; mf < 4; mf++) abase[mf] = sbase + aoff + rA[mf] * 128;
#pragma unroll
        for (int nh = 0; nh < 2; nh++) bbase[nh] = sbase + boff + rB[nh] * 128;

        int kend = (kt == 4) ? 32 : 64;
#pragma unroll
        for (int ks = 0; ks < 64; ks += 16) {
            if (ks >= kend) break;
            uint32_t cofs = ((uint32_t)(ks * 2) + kadd) ^ xorv;
            unsigned a[4][4];
#pragma unroll
            for (int mf = 0; mf < 4; mf++)
                ldsm_x4(a[mf][0], a[mf][1], a[mf][2], a[mf][3], abase[mf] + cofs);
            unsigned b[4][2];
#pragma unroll
            for (int nh = 0; nh < 2; nh++) {
                unsigned r0, r1, r2, r3;
                ldsm_x4(r0, r1, r2, r3, bbase[nh] + cofs);
                b[nh * 2][0] = r0; b[nh * 2 + 1][0] = r1;
                b[nh * 2][1] = r2; b[nh * 2 + 1][1] = r3;
            }
#pragma unroll
            for (int mf = 0; mf < 4; mf++)
#pragma unroll
                for (int nf = 0; nf < 4; nf++)
                    mma16816(acc[mf][nf], a[mf], b[nf]);
        }
        __syncthreads();
    }

    // ---- fused epilogue ----
    int j0 = tg * 2;
    if (!isK) {
        float qp[8][4];
#pragma unroll
        for (int a1 = 0; a1 < 8; a1++)
#pragma unroll
            for (int a2 = 0; a2 < 4; a2++) qp[a1][a2] = 0.f;
#pragma unroll
        for (int p = 0; p < 2; p++) {
            int sl16 = (wn * 2 + p) * 16;
            float b0 = bias_s[sl16 + j0];
            float b1 = bias_s[sl16 + j0 + 1];
            float b2 = bias_s[sl16 + j0 + 8];
            float b3 = bias_s[sl16 + j0 + 9];
#pragma unroll
            for (int mf = 0; mf < 4; mf++) {
#pragma unroll
                for (int h = 0; h < 2; h++) {
                    float v0 = acc[mf][2 * p][2 * h] + b0;
                    float v1 = acc[mf][2 * p][2 * h + 1] + b1;
                    float v2 = acc[mf][2 * p + 1][2 * h] + b2;
                    float v3 = acc[mf][2 * p + 1][2 * h + 1] + b3;
                    float ssq = v0 * v0 + v1 * v1 + v2 * v2 + v3 * v3;
                    ssq += __shfl_xor_sync(0xffffffffu, ssq, 1);
                    ssq += __shfl_xor_sync(0xffffffffu, ssq, 2);
                    float inv = 1.f / fmaxf(sqrtf(ssq), 1e-12f);
                    qp[mf * 2 + h][0] += v0 * inv;
                    qp[mf * 2 + h][1] += v1 * inv;
                    qp[mf * 2 + h][2] += v2 * inv;
                    qp[mf * 2 + h][3] += v3 * inv;
                }
            }
        }
#pragma unroll
        for (int mf = 0; mf < 4; mf++) {
#pragma unroll
            for (int h = 0; h < 2; h++) {
                int row = wm * 64 + mf * 16 + gr + h * 8;
                atomicAdd(&qs_s[row * QSP + j0],     qp[mf * 2 + h][0]);
                atomicAdd(&qs_s[row * QSP + j0 + 1], qp[mf * 2 + h][1]);
                atomicAdd(&qs_s[row * QSP + j0 + 8], qp[mf * 2 + h][2]);
                atomicAdd(&qs_s[row * QSP + j0 + 9], qp[mf * 2 + h][3]);
            }
        }
        __syncthreads();
        for (int idx = tid; idx < GBM * SQG; idx += 256) {
            int row = idx >> 4, col = idx & 15;
            atomicAdd(&g_qsum[(size_t)(m0 + row) * SQG + col], qs_s[row * QSP + col]);
        }
        __threadfence();          // make this thread's g_qsum updates visible
        __syncthreads();          // all threads' fences complete
        if (tid == 0) atomicAdd(&g_qcnt, 1u);
    } else {
        // wait for all q-blocks (their MMA time already overlapped ours)
        if (tid == 0) {
            while (atomicAdd(&g_qcnt, 0u) < (unsigned)NQBLK) __nanosleep(100);
        }
        __syncthreads();
#pragma unroll
        for (int mf = 0; mf < 4; mf++) {
#pragma unroll
            for (int h = 0; h < 2; h++) {
                int row = wm * 64 + mf * 16 + gr + h * 8;
                const float* qsr = &g_qsum[(size_t)(m0 + row) * SQG];
                float q0 = qsr[j0], q1 = qsr[j0 + 1], q2 = qsr[j0 + 8], q3 = qsr[j0 + 9];
#pragma unroll
                for (int p = 0; p < 2; p++) {
                    int sl16 = (wn * 2 + p) * 16;
                    float v0 = acc[mf][2 * p][2 * h] + bias_s[sl16 + j0];
                    float v1 = acc[mf][2 * p][2 * h + 1] + bias_s[sl16 + j0 + 1];
                    float v2 = acc[mf][2 * p + 1][2 * h] + bias_s[sl16 + j0 + 8];
                    float v3 = acc[mf][2 * p + 1][2 * h + 1] + bias_s[sl16 + j0 + 9];
                    float ssq = v0 * v0 + v1 * v1 + v2 * v2 + v3 * v3;
                    float dl  = v0 * q0 + v1 * q1 + v2 * q2 + v3 * q3;
                    ssq += __shfl_xor_sync(0xffffffffu, ssq, 1);
                    ssq += __shfl_xor_sync(0xffffffffu, ssq, 2);
                    dl  += __shfl_xor_sync(0xffffffffu, dl, 1);
                    dl  += __shfl_xor_sync(0xffffffffu, dl, 2);
                    float inv = 1.f / fmaxf(sqrtf(ssq), 1e-12f);
                    if (tg == 0)
                        g_attn[(size_t)(m0 + row) * NMEM + slot0 + wn * 2 + p] =
                            dl * inv * (1.f / 64.f);
                }
            }
        }
    }
}

// ---------------- output: out = x + attn @ Wv + bout, written [B,256,H,W] ----------------
__global__ __launch_bounds__(256) void out_kernel(const float* __restrict__ x,
                                                  const float* __restrict__ bout,
                                                  float* __restrict__ out) {
    __shared__ float attn_s[64][65];
    __shared__ __align__(16) float wv_s[64][32];
    int p0 = blockIdx.x * 64;
    int o0 = blockIdx.y * 32;
    int tid = threadIdx.x;
    int px = tid & 63, oq = tid >> 6;

#pragma unroll
    for (int i = 0; i < 16; i++) {
        int idx = tid + i * 256;
        int pr = idx >> 6, mm = idx & 63;
        attn_s[pr][mm] = g_attn[(size_t)(p0 + pr) * NMEM + mm];
    }
#pragma unroll
    for (int i = 0; i < 8; i++) {
        int idx = tid + i * 256;
        int mm = idx >> 5, oo = idx & 31;
        wv_s[mm][oo] = g_Wv[mm * CCH + o0 + oo];
    }
    __syncthreads();

    float acc[8];
#pragma unroll
    for (int i = 0; i < 8; i++) acc[i] = 0.f;

#pragma unroll 4
    for (int m = 0; m < 64; m++) {
        float a = attn_s[px][m];
        float4 w0 = *reinterpret_cast<const float4*>(&wv_s[m][oq * 8]);
        float4 w1 = *reinterpret_cast<const float4*>(&wv_s[m][oq * 8 + 4]);
        acc[0] += a * w0.x; acc[1] += a * w0.y; acc[2] += a * w0.z; acc[3] += a * w0.w;
        acc[4] += a * w1.x; acc[5] += a * w1.y; acc[6] += a * w1.z; acc[7] += a * w1.w;
    }

    int p = p0 + px;
    int b = p >> 12, s = p & (SS - 1);
#pragma unroll
    for (int i = 0; i < 8; i++) {
        int o = o0 + oq * 8 + i;
        size_t gi = ((size_t)b * CCH + o) * SS + s;
        out[gi] = x[gi] + acc[i] + bout[o];
    }
}

// ---------------- launch ----------------
extern "C" void kernel_launch(void* const* d_in, const int* in_sizes, int n_in,
                              void* d_out, int out_size) {
    const float* x    = (const float*)d_in[0];
    const float* pos  = (const float*)d_in[1];
    const float* wq   = (const float*)d_in[2];
    const float* bq   = (const float*)d_in[3];
    const float* wk   = (const float*)d_in[4];
    const float* bk   = (const float*)d_in[5];
    const float* v    = (const float*)d_in[6];
    const float* wout = (const float*)d_in[7];
    const float* bout = (const float*)d_in[8];
    float* out = (float*)d_out;

    cudaFuncSetAttribute(gemm_qk_kernel,
                         cudaFuncAttributeMaxDynamicSharedMemorySize, SM_TOTAL);
    void* qsum_ptr = nullptr;
    void* qcnt_ptr = nullptr;
    cudaGetSymbolAddress(&qsum_ptr, g_qsum);
    cudaGetSymbolAddress(&qcnt_ptr, g_qcnt);

    prep_x_kernel<<<dim3(CCH / 32, SS / 32, BB), 256>>>(x);
    prep_pos_kernel<<<(MP * 32) / 256, 256>>>(pos);
    prep_w_kernel<<<(QKROWS * KPAD) / 256, 256>>>(wq, wk);
    prep_wv_kernel<<<dim3(NMEM, 16), 256>>>(v, wout);
    cudaMemsetAsync(qsum_ptr, 0, (size_t)MP * SQG * sizeof(float), 0);
    cudaMemsetAsync(qcnt_ptr, 0, sizeof(unsigned), 0);
    gemm_qk_kernel<<<dim3(MP / GBM, 16), 256, SM_TOTAL>>>(bq, bk);
    out_kernel<<<dim3(MP / 64, CCH / 32), 256>>>(x, bout, out);
}

// round 16
// speedup vs baseline: 1.0588x; 1.0588x over previous
#include <cuda_runtime.h>
#include <cuda_bf16.h>
#include <stdint.h>

// ---------------- problem constants ----------------
#define BB     4
#define CCH    256          // FIN
#define SS     4096         // H*W
#define MP     (BB*SS)      // 16384 positions
#define NMEM   64
#define SQG    16
#define QKROWS 2048         // 1024 q rows + 1024 k rows
#define CINR   258          // FIN + 2 pos channels
#define KPAD   288          // CINR padded: 4x64 + 1x32 k-tiles
#define NKT    5

// ---------------- scratch (device globals; no allocation) ----------------
__device__ __nv_bfloat16 g_A[(size_t)MP * KPAD];          // xp^T bf16, K padded
__device__ __nv_bfloat16 g_W[(size_t)QKROWS * KPAD];      // [wq; wk] bf16, K padded
__device__ float         g_qsum[(size_t)MP * SQG];        // sum over slots of normalized q
__device__ float         g_attn[(size_t)MP * NMEM];       // attn_mean per position
__device__ float         g_Wv[NMEM * CCH];                // v @ wout^T (fused tail)

// ---------------- PTX helpers (base sm_103 only) ----------------
__device__ __forceinline__ uint32_t smem_u32(const void* p) {
    uint32_t a;
    asm("{ .reg .u64 t; cvta.to.shared.u64 t, %1; cvt.u32.u64 %0, t; }" : "=r"(a) : "l"(p));
    return a;
}
__device__ __forceinline__ void cp16(uint32_t saddr, const void* g) {
    asm volatile("cp.async.cg.shared.global [%0], [%1], 16;\n" :: "r"(saddr), "l"(g));
}
__device__ __forceinline__ void cp_commit() {
    asm volatile("cp.async.commit_group;\n" ::: "memory");
}
template <int N> __device__ __forceinline__ void cp_wait() {
    asm volatile("cp.async.wait_group %0;\n" :: "n"(N) : "memory");
}
__device__ __forceinline__ void mma16816(float* c, const unsigned* a, const unsigned* b) {
    asm volatile(
        "mma.sync.aligned.m16n8k16.row.col.f32.bf16.bf16.f32 "
        "{%0,%1,%2,%3}, {%4,%5,%6,%7}, {%8,%9}, {%0,%1,%2,%3};\n"
        : "+f"(c[0]), "+f"(c[1]), "+f"(c[2]), "+f"(c[3])
        : "r"(a[0]), "r"(a[1]), "r"(a[2]), "r"(a[3]), "r"(b[0]), "r"(b[1]));
}
__device__ __forceinline__ void ldsm_x4(unsigned& r0, unsigned& r1, unsigned& r2,
                                        unsigned& r3, uint32_t a) {
    asm volatile("ldmatrix.sync.aligned.m8n8.x4.shared.b16 {%0,%1,%2,%3}, [%4];"
                 : "=r"(r0), "=r"(r1), "=r"(r2), "=r"(r3) : "r"(a));
}
// SW128 swizzle for 128-byte rows
__device__ __forceinline__ uint32_t swz(uint32_t off) { return off ^ ((off >> 3) & 0x70); }

// ---------------- fused prep: all independent prep work in ONE launch ----------------
// blocks [0,4096)      : transpose x -> g_A cols 0..255      (8 x 128 x 4 tiles)
// blocks [4096,6144)   : pos channels + zero pad cols 256..287
// blocks [6144,8448)   : weights [wq;wk] -> g_W bf16 padded
// blocks [8448,8704)   : Wv[m][o] = sum_f v[m][f]*wout[o][f]
#define PREP_BLOCKS 8704

__global__ __launch_bounds__(256) void prep_all_kernel(
    const float* __restrict__ x,    const float* __restrict__ pos,
    const float* __restrict__ wq,   const float* __restrict__ wk,
    const float* __restrict__ v,    const float* __restrict__ wout) {
    __shared__ float smbuf[1056];   // 32x33 tile / (vs[256]+part[256]) union
    int bid = blockIdx.x, tid = threadIdx.x;

    if (bid < 4096) {
        // ---- transpose x (vectorized) ----
        int cx = bid & 7, sy = (bid >> 3) & 127, b = bid >> 10;
        int c0 = cx * 32, s0 = sy * 32;
        float (*tile)[33] = reinterpret_cast<float(*)[33]>(smbuf);
        {
            int row = tid >> 3, col = (tid & 7) * 4;
            float4 vv = *reinterpret_cast<const float4*>(
                &x[((size_t)b * CCH + c0 + row) * SS + s0 + col]);
            tile[row][col]     = vv.x; tile[row][col + 1] = vv.y;
            tile[row][col + 2] = vv.z; tile[row][col + 3] = vv.w;
        }
        __syncthreads();
        {
            int si = tid >> 3, c4 = (tid & 7) * 4;
            int p = b * SS + s0 + si;
            __nv_bfloat16 h[4];
#pragma unroll
            for (int j = 0; j < 4; j++) h[j] = __float2bfloat16(tile[c4 + j][si]);
            *reinterpret_cast<uint2*>(&g_A[(size_t)p * KPAD + c0 + c4]) =
                *reinterpret_cast<uint2*>(h);
        }
    } else if (bid < 6144) {
        // ---- pos channels + zero pad ----
        int g = (bid - 4096) * 256 + tid;    // MP*32
        int p = g >> 5, cc = g & 31;
        int s = p & (SS - 1);
        float vv = 0.f;
        if (cc == 0)      vv = pos[s];
        else if (cc == 1) vv = pos[SS + s];
        g_A[(size_t)p * KPAD + 256 + cc] = __float2bfloat16(vv);
    } else if (bid < 8448) {
        // ---- weights -> bf16 padded ----
        int g = (bid - 6144) * 256 + tid;    // QKROWS*KPAD
        int r = g / KPAD, c = g % KPAD;
        float vv = 0.f;
        if (c < CINR) vv = (r < 1024) ? wq[r * CINR + c] : wk[(r - 1024) * CINR + c];
        g_W[g] = __float2bfloat16(vv);
    } else {
        // ---- Wv = v @ wout^T ----
        int b2 = bid - 8448;                 // [0,256)
        int m = b2 >> 2, oc = b2 & 3;
        float* vs = smbuf;
        float* part = smbuf + 256;
        int ol = tid & 63, fq = tid >> 6;
        vs[tid] = v[m * CCH + tid];
        __syncthreads();
        int o = oc * 64 + ol;
        const float4* wr = reinterpret_cast<const float4*>(wout + (size_t)o * CCH + fq * 64);
        float acc = 0.f;
#pragma unroll
        for (int i = 0; i < 16; i++) {
            float4 w = wr[i];
            int f = fq * 64 + i * 4;
            acc += vs[f] * w.x + vs[f + 1] * w.y + vs[f + 2] * w.z + vs[f + 3] * w.w;
        }
        part[tid] = acc;
        __syncthreads();
        if (fq == 0)
            g_Wv[m * CCH + o] = part[ol] + part[ol + 64] + part[ol + 128] + part[ol + 192];
    }
}

// ---------------- fused GEMM + normalization epilogues (two launches) ----------------
//   launch 0 (q): n rows [0,1024).   Epilogue: per-slot normalize (quad shuffle),
//                 accumulate sum of normalized q, atomic-flush to g_qsum.
//   launch 1 (k): n rows [1024,2048). Epilogue: normalize k, dot with g_qsum,
//                 write g_attn directly.
#define GBM 128
#define GBN 128
#define STAGE_A   16384
#define SM_AOFF(s) ((s) * STAGE_A)
#define SM_BOFF(s) (32768 + (s) * STAGE_A)
#define QS_OFF    65536                 // 128 x 17 x 4 = 8704
#define BIAS_OFF  74240                 // 128 x 4 = 512 (this block's slots)
#define SM_TOTAL  74752
#define QSP       17

__device__ __forceinline__ void stage_tile(uint32_t sbase, uint32_t aoff, uint32_t boff,
                                           int m0, int n0, int kt, int tid) {
    int kk = kt * 64;
    if (kt < 4) {
#pragma unroll
        for (int i = 0; i < 4; i++) {
            int idx = tid + i * 256;
            int row = idx >> 3, ch = idx & 7;
            uint32_t so = swz(row * 128 + ch * 16);
            cp16(sbase + aoff + so, &g_A[(size_t)(m0 + row) * KPAD + kk + ch * 8]);
            cp16(sbase + boff + so, &g_W[(size_t)(n0 + row) * KPAD + kk + ch * 8]);
        }
    } else {
#pragma unroll
        for (int i = 0; i < 2; i++) {
            int idx = tid + i * 256;
            int row = idx >> 2, ch = idx & 3;
            uint32_t so = swz(row * 128 + ch * 16);
            cp16(sbase + aoff + so, &g_A[(size_t)(m0 + row) * KPAD + kk + ch * 8]);
            cp16(sbase + boff + so, &g_W[(size_t)(n0 + row) * KPAD + kk + ch * 8]);
        }
    }
    cp_commit();
}

__global__ __launch_bounds__(256, 2) void gemm_qk_kernel(int nbase, int isK,
                                                         const float* __restrict__ bias) {
    extern __shared__ __align__(1024) char smem[];
    uint32_t sbase = smem_u32(smem);
    float* qs_s   = reinterpret_cast<float*>(smem + QS_OFF);
    float* bias_s = reinterpret_cast<float*>(smem + BIAS_OFF);
    int tid  = threadIdx.x;
    int warp = tid >> 5, lane = tid & 31;
    int wm = warp & 1, wn = warp >> 1;      // warp grid 2(m) x 4(n)
    int gr = lane >> 2, tg = lane & 3;
    int m0 = blockIdx.x * GBM;
    int n0 = nbase + blockIdx.y * GBN;
    int slot0 = blockIdx.y * 8;             // first slot handled by this block

    // ldmatrix lane geometry
    int j  = lane >> 3;
    int jm = j & 1;
    uint32_t kadd = (uint32_t)(j >> 1) * 16;
    uint32_t xorv = (uint32_t)(lane & 7) << 4;
    int rA[4], rB[2];
#pragma unroll
    for (int mf = 0; mf < 4; mf++) rA[mf] = wm * 64 + mf * 16 + jm * 8 + (lane & 7);
#pragma unroll
    for (int nh = 0; nh < 2; nh++) rB[nh] = wn * 32 + nh * 16 + jm * 8 + (lane & 7);

    float acc[4][4][4];
#pragma unroll
    for (int i = 0; i < 4; i++)
#pragma unroll
        for (int jj = 0; jj < 4; jj++)
#pragma unroll
            for (int q = 0; q < 4; q++) acc[i][jj][q] = 0.f;

    // prologue: stage tile 0; zero qs smem; load this block's 128 bias values
    stage_tile(sbase, SM_AOFF(0), SM_BOFF(0), m0, n0, 0, tid);
    for (int i = tid; i < GBM * QSP; i += 256) qs_s[i] = 0.f;
    if (tid < 128) bias_s[tid] = bias[slot0 * 16 + tid];

    for (int kt = 0; kt < NKT; kt++) {
        uint32_t aoff = SM_AOFF(kt & 1);
        uint32_t boff = SM_BOFF(kt & 1);
        if (kt + 1 < NKT) {
            stage_tile(sbase, SM_AOFF((kt + 1) & 1), SM_BOFF((kt + 1) & 1),
                       m0, n0, kt + 1, tid);
            cp_wait<1>();
        } else {
            cp_wait<0>();
        }
        __syncthreads();

        uint32_t abase[4], bbase[2];
#pragma unroll
        for (int mf = 0; mf < 4; mf++) abase[mf] = sbase + aoff + rA[mf] * 128;
#pragma unroll
        for (int nh = 0; nh < 2; nh++) bbase[nh] = sbase + boff + rB[nh] * 128;

        int kend = (kt == 4) ? 32 : 64;
#pragma unroll
        for (int ks = 0; ks < 64; ks += 16) {
            if (ks >= kend) break;
            uint32_t cofs = ((uint32_t)(ks * 2) + kadd) ^ xorv;
            unsigned a[4][4];
#pragma unroll
            for (int mf = 0; mf < 4; mf++)
                ldsm_x4(a[mf][0], a[mf][1], a[mf][2], a[mf][3], abase[mf] + cofs);
            unsigned b[4][2];
#pragma unroll
            for (int nh = 0; nh < 2; nh++) {
                unsigned r0, r1, r2, r3;
                ldsm_x4(r0, r1, r2, r3, bbase[nh] + cofs);
                b[nh * 2][0] = r0; b[nh * 2 + 1][0] = r1;
                b[nh * 2][1] = r2; b[nh * 2 + 1][1] = r3;
            }
#pragma unroll
            for (int mf = 0; mf < 4; mf++)
#pragma unroll
                for (int nf = 0; nf < 4; nf++)
                    mma16816(acc[mf][nf], a[mf], b[nf]);
        }
        __syncthreads();
    }

    // ---- fused epilogue ----
    int j0 = tg * 2;
    if (!isK) {
        float qp[8][4];
#pragma unroll
        for (int a1 = 0; a1 < 8; a1++)
#pragma unroll
            for (int a2 = 0; a2 < 4; a2++) qp[a1][a2] = 0.f;
#pragma unroll
        for (int p = 0; p < 2; p++) {
            int sl16 = (wn * 2 + p) * 16;
            float b0 = bias_s[sl16 + j0];
            float b1 = bias_s[sl16 + j0 + 1];
            float b2 = bias_s[sl16 + j0 + 8];
            float b3 = bias_s[sl16 + j0 + 9];
#pragma unroll
            for (int mf = 0; mf < 4; mf++) {
#pragma unroll
                for (int h = 0; h < 2; h++) {
                    float v0 = acc[mf][2 * p][2 * h] + b0;
                    float v1 = acc[mf][2 * p][2 * h + 1] + b1;
                    float v2 = acc[mf][2 * p + 1][2 * h] + b2;
                    float v3 = acc[mf][2 * p + 1][2 * h + 1] + b3;
                    float ssq = v0 * v0 + v1 * v1 + v2 * v2 + v3 * v3;
                    ssq += __shfl_xor_sync(0xffffffffu, ssq, 1);
                    ssq += __shfl_xor_sync(0xffffffffu, ssq, 2);
                    float inv = 1.f / fmaxf(sqrtf(ssq), 1e-12f);
                    qp[mf * 2 + h][0] += v0 * inv;
                    qp[mf * 2 + h][1] += v1 * inv;
                    qp[mf * 2 + h][2] += v2 * inv;
                    qp[mf * 2 + h][3] += v3 * inv;
                }
            }
        }
#pragma unroll
        for (int mf = 0; mf < 4; mf++) {
#pragma unroll
            for (int h = 0; h < 2; h++) {
                int row = wm * 64 + mf * 16 + gr + h * 8;
                atomicAdd(&qs_s[row * QSP + j0],     qp[mf * 2 + h][0]);
                atomicAdd(&qs_s[row * QSP + j0 + 1], qp[mf * 2 + h][1]);
                atomicAdd(&qs_s[row * QSP + j0 + 8], qp[mf * 2 + h][2]);
                atomicAdd(&qs_s[row * QSP + j0 + 9], qp[mf * 2 + h][3]);
            }
        }
        __syncthreads();
        for (int idx = tid; idx < GBM * SQG; idx += 256) {
            int row = idx >> 4, col = idx & 15;
            atomicAdd(&g_qsum[(size_t)(m0 + row) * SQG + col], qs_s[row * QSP + col]);
        }
    } else {
#pragma unroll
        for (int mf = 0; mf < 4; mf++) {
#pragma unroll
            for (int h = 0; h < 2; h++) {
                int row = wm * 64 + mf * 16 + gr + h * 8;
                const float* qsr = &g_qsum[(size_t)(m0 + row) * SQG];
                float q0 = qsr[j0], q1 = qsr[j0 + 1], q2 = qsr[j0 + 8], q3 = qsr[j0 + 9];
#pragma unroll
                for (int p = 0; p < 2; p++) {
                    int sl16 = (wn * 2 + p) * 16;
                    float v0 = acc[mf][2 * p][2 * h] + bias_s[sl16 + j0];
                    float v1 = acc[mf][2 * p][2 * h + 1] + bias_s[sl16 + j0 + 1];
                    float v2 = acc[mf][2 * p + 1][2 * h] + bias_s[sl16 + j0 + 8];
                    float v3 = acc[mf][2 * p + 1][2 * h + 1] + bias_s[sl16 + j0 + 9];
                    float ssq = v0 * v0 + v1 * v1 + v2 * v2 + v3 * v3;
                    float dl  = v0 * q0 + v1 * q1 + v2 * q2 + v3 * q3;
                    ssq += __shfl_xor_sync(0xffffffffu, ssq, 1);
                    ssq += __shfl_xor_sync(0xffffffffu, ssq, 2);
                    dl  += __shfl_xor_sync(0xffffffffu, dl, 1);
                    dl  += __shfl_xor_sync(0xffffffffu, dl, 2);
                    float inv = 1.f / fmaxf(sqrtf(ssq), 1e-12f);
                    if (tg == 0)
                        g_attn[(size_t)(m0 + row) * NMEM + slot0 + wn * 2 + p] =
                            dl * inv * (1.f / 64.f);
                }
            }
        }
    }
}

// ---------------- output: out = x + attn @ Wv + bout, written [B,256,H,W] ----------------
__global__ __launch_bounds__(256) void out_kernel(const float* __restrict__ x,
                                                  const float* __restrict__ bout,
                                                  float* __restrict__ out) {
    __shared__ float attn_s[64][65];
    __shared__ __align__(16) float wv_s[64][32];
    int p0 = blockIdx.x * 64;
    int o0 = blockIdx.y * 32;
    int tid = threadIdx.x;
    int px = tid & 63, oq = tid >> 6;

#pragma unroll
    for (int i = 0; i < 16; i++) {
        int idx = tid + i * 256;
        int pr = idx >> 6, mm = idx & 63;
        attn_s[pr][mm] = g_attn[(size_t)(p0 + pr) * NMEM + mm];
    }
#pragma unroll
    for (int i = 0; i < 8; i++) {
        int idx = tid + i * 256;
        int mm = idx >> 5, oo = idx & 31;
        wv_s[mm][oo] = g_Wv[mm * CCH + o0 + oo];
    }
    __syncthreads();

    float acc[8];
#pragma unroll
    for (int i = 0; i < 8; i++) acc[i] = 0.f;

#pragma unroll 4
    for (int m = 0; m < 64; m++) {
        float a = attn_s[px][m];
        float4 w0 = *reinterpret_cast<const float4*>(&wv_s[m][oq * 8]);
        float4 w1 = *reinterpret_cast<const float4*>(&wv_s[m][oq * 8 + 4]);
        acc[0] += a * w0.x; acc[1] += a * w0.y; acc[2] += a * w0.z; acc[3] += a * w0.w;
        acc[4] += a * w1.x; acc[5] += a * w1.y; acc[6] += a * w1.z; acc[7] += a * w1.w;
    }

    int p = p0 + px;
    int b = p >> 12, s = p & (SS - 1);
#pragma unroll
    for (int i = 0; i < 8; i++) {
        int o = o0 + oq * 8 + i;
        size_t gi = ((size_t)b * CCH + o) * SS + s;
        out[gi] = x[gi] + acc[i] + bout[o];
    }
}

// ---------------- launch ----------------
extern "C" void kernel_launch(void* const* d_in, const int* in_sizes, int n_in,
                              void* d_out, int out_size) {
    const float* x    = (const float*)d_in[0];
    const float* pos  = (const float*)d_in[1];
    const float* wq   = (const float*)d_in[2];
    const float* bq   = (const float*)d_in[3];
    const float* wk   = (const float*)d_in[4];
    const float* bk   = (const float*)d_in[5];
    const float* v    = (const float*)d_in[6];
    const float* wout = (const float*)d_in[7];
    const float* bout = (const float*)d_in[8];
    float* out = (float*)d_out;

    cudaFuncSetAttribute(gemm_qk_kernel,
                         cudaFuncAttributeMaxDynamicSharedMemorySize, SM_TOTAL);
    void* qsum_ptr = nullptr;
    cudaGetSymbolAddress(&qsum_ptr, g_qsum);

    prep_all_kernel<<<PREP_BLOCKS, 256>>>(x, pos, wq, wk, v, wout);
    cudaMemsetAsync(qsum_ptr, 0, (size_t)MP * SQG * sizeof(float), 0);
    gemm_qk_kernel<<<dim3(MP / GBM, 8), 256, SM_TOTAL>>>(0, 0, bq);
    gemm_qk_kernel<<<dim3(MP / GBM, 8), 256, SM_TOTAL>>>(1024, 1, bk);
    out_kernel<<<dim3(MP / 64, CCH / 32), 256>>>(x, bout, out);
}

// round 17
// speedup vs baseline: 1.1071x; 1.0456x over previous
#include <cuda_runtime.h>
#include <cuda_bf16.h>
#include <stdint.h>

// ---------------- problem constants ----------------
#define BB     4
#define CCH    256          // FIN
#define SS     4096         // H*W
#define MP     (BB*SS)      // 16384 positions
#define NMEM   64
#define SQG    16
#define QKROWS 2048         // 1024 q rows + 1024 k rows
#define CINR   258          // FIN + 2 pos channels
#define KPAD   288          // CINR padded: 4x64 + 1x32 k-tiles
#define NKT    5

// ---------------- scratch (device globals; no allocation) ----------------
__device__ __nv_bfloat16 g_A[(size_t)MP * KPAD];          // xp^T bf16, K padded
__device__ __nv_bfloat16 g_W[(size_t)QKROWS * KPAD];      // [wq; wk] bf16, K padded
__device__ float         g_qsum[(size_t)MP * SQG];        // sum over slots of normalized q
__device__ float         g_attn[(size_t)MP * NMEM];       // attn_mean per position
__device__ float         g_Wv[NMEM * CCH];                // v @ wout^T (fused tail)

// ---------------- PTX helpers (base sm_103 only) ----------------
__device__ __forceinline__ uint32_t smem_u32(const void* p) {
    uint32_t a;
    asm("{ .reg .u64 t; cvta.to.shared.u64 t, %1; cvt.u32.u64 %0, t; }" : "=r"(a) : "l"(p));
    return a;
}
__device__ __forceinline__ void cp16(uint32_t saddr, const void* g) {
    asm volatile("cp.async.cg.shared.global [%0], [%1], 16;\n" :: "r"(saddr), "l"(g));
}
__device__ __forceinline__ void cp_commit() {
    asm volatile("cp.async.commit_group;\n" ::: "memory");
}
template <int N> __device__ __forceinline__ void cp_wait() {
    asm volatile("cp.async.wait_group %0;\n" :: "n"(N) : "memory");
}
__device__ __forceinline__ void mma16816(float* c, const unsigned* a, const unsigned* b) {
    asm volatile(
        "mma.sync.aligned.m16n8k16.row.col.f32.bf16.bf16.f32 "
        "{%0,%1,%2,%3}, {%4,%5,%6,%7}, {%8,%9}, {%0,%1,%2,%3};\n"
        : "+f"(c[0]), "+f"(c[1]), "+f"(c[2]), "+f"(c[3])
        : "r"(a[0]), "r"(a[1]), "r"(a[2]), "r"(a[3]), "r"(b[0]), "r"(b[1]));
}
__device__ __forceinline__ void ldsm_x4(unsigned& r0, unsigned& r1, unsigned& r2,
                                        unsigned& r3, uint32_t a) {
    asm volatile("ldmatrix.sync.aligned.m8n8.x4.shared.b16 {%0,%1,%2,%3}, [%4];"
                 : "=r"(r0), "=r"(r1), "=r"(r2), "=r"(r3) : "r"(a));
}
// SW128 swizzle for 128-byte rows
__device__ __forceinline__ uint32_t swz(uint32_t off) { return off ^ ((off >> 3) & 0x70); }

// packed f32x2 helpers (Blackwell base-family PTX; HW FFMA2)
typedef unsigned long long u64t;
__device__ __forceinline__ u64t pack2(float lo, float hi) {
    u64t r;
    asm("mov.b64 %0, {%1, %2};" : "=l"(r) : "f"(lo), "f"(hi));
    return r;
}
__device__ __forceinline__ void unpack2(u64t v, float& lo, float& hi) {
    asm("mov.b64 {%0, %1}, %2;" : "=f"(lo), "=f"(hi) : "l"(v));
}
__device__ __forceinline__ u64t ffma2p(u64t a, u64t b, u64t c) {
    u64t d;
    asm("fma.rn.f32x2 %0, %1, %2, %3;" : "=l"(d) : "l"(a), "l"(b), "l"(c));
    return d;
}

// ---------------- fused prep: all independent prep work in ONE launch ----------------
// blocks [0,4096)      : transpose x -> g_A cols 0..255
// blocks [4096,6144)   : pos channels + zero pad cols 256..287
// blocks [6144,8448)   : weights [wq;wk] -> g_W bf16 padded
// blocks [8448,8704)   : Wv[m][o] = sum_f v[m][f]*wout[o][f]
#define PREP_BLOCKS 8704

__global__ __launch_bounds__(256) void prep_all_kernel(
    const float* __restrict__ x,    const float* __restrict__ pos,
    const float* __restrict__ wq,   const float* __restrict__ wk,
    const float* __restrict__ v,    const float* __restrict__ wout) {
    __shared__ float smbuf[1056];   // 32x33 tile / (vs[256]+part[256]) union
    int bid = blockIdx.x, tid = threadIdx.x;

    if (bid < 4096) {
        int cx = bid & 7, sy = (bid >> 3) & 127, b = bid >> 10;
        int c0 = cx * 32, s0 = sy * 32;
        float (*tile)[33] = reinterpret_cast<float(*)[33]>(smbuf);
        {
            int row = tid >> 3, col = (tid & 7) * 4;
            float4 vv = *reinterpret_cast<const float4*>(
                &x[((size_t)b * CCH + c0 + row) * SS + s0 + col]);
            tile[row][col]     = vv.x; tile[row][col + 1] = vv.y;
            tile[row][col + 2] = vv.z; tile[row][col + 3] = vv.w;
        }
        __syncthreads();
        {
            int si = tid >> 3, c4 = (tid & 7) * 4;
            int p = b * SS + s0 + si;
            __nv_bfloat16 h[4];
#pragma unroll
            for (int j = 0; j < 4; j++) h[j] = __float2bfloat16(tile[c4 + j][si]);
            *reinterpret_cast<uint2*>(&g_A[(size_t)p * KPAD + c0 + c4]) =
                *reinterpret_cast<uint2*>(h);
        }
    } else if (bid < 6144) {
        int g = (bid - 4096) * 256 + tid;
        int p = g >> 5, cc = g & 31;
        int s = p & (SS - 1);
        float vv = 0.f;
        if (cc == 0)      vv = pos[s];
        else if (cc == 1) vv = pos[SS + s];
        g_A[(size_t)p * KPAD + 256 + cc] = __float2bfloat16(vv);
    } else if (bid < 8448) {
        int g = (bid - 6144) * 256 + tid;
        int r = g / KPAD, c = g % KPAD;
        float vv = 0.f;
        if (c < CINR) vv = (r < 1024) ? wq[r * CINR + c] : wk[(r - 1024) * CINR + c];
        g_W[g] = __float2bfloat16(vv);
    } else {
        int b2 = bid - 8448;
        int m = b2 >> 2, oc = b2 & 3;
        float* vs = smbuf;
        float* part = smbuf + 256;
        int ol = tid & 63, fq = tid >> 6;
        vs[tid] = v[m * CCH + tid];
        __syncthreads();
        int o = oc * 64 + ol;
        const float4* wr = reinterpret_cast<const float4*>(wout + (size_t)o * CCH + fq * 64);
        float acc = 0.f;
#pragma unroll
        for (int i = 0; i < 16; i++) {
            float4 w = wr[i];
            int f = fq * 64 + i * 4;
            acc += vs[f] * w.x + vs[f + 1] * w.y + vs[f + 2] * w.z + vs[f + 3] * w.w;
        }
        part[tid] = acc;
        __syncthreads();
        if (fq == 0)
            g_Wv[m * CCH + o] = part[ol] + part[ol + 64] + part[ol + 128] + part[ol + 192];
    }
}

// ---------------- fused GEMM + normalization epilogues (two launches) ----------------
#define GBM 128
#define GBN 128
#define STAGE_A   16384
#define SM_AOFF(s) ((s) * STAGE_A)
#define SM_BOFF(s) (32768 + (s) * STAGE_A)
#define QS_OFF    65536                 // 128 x 17 x 4 = 8704
#define BIAS_OFF  74240                 // 128 x 4 = 512 (this block's slots)
#define SM_TOTAL  74752
#define QSP       17

__device__ __forceinline__ void stage_tile(uint32_t sbase, uint32_t aoff, uint32_t boff,
                                           int m0, int n0, int kt, int tid) {
    int kk = kt * 64;
    if (kt < 4) {
#pragma unroll
        for (int i = 0; i < 4; i++) {
            int idx = tid + i * 256;
            int row = idx >> 3, ch = idx & 7;
            uint32_t so = swz(row * 128 + ch * 16);
            cp16(sbase + aoff + so, &g_A[(size_t)(m0 + row) * KPAD + kk + ch * 8]);
            cp16(sbase + boff + so, &g_W[(size_t)(n0 + row) * KPAD + kk + ch * 8]);
        }
    } else {
#pragma unroll
        for (int i = 0; i < 2; i++) {
            int idx = tid + i * 256;
            int row = idx >> 2, ch = idx & 3;
            uint32_t so = swz(row * 128 + ch * 16);
            cp16(sbase + aoff + so, &g_A[(size_t)(m0 + row) * KPAD + kk + ch * 8]);
            cp16(sbase + boff + so, &g_W[(size_t)(n0 + row) * KPAD + kk + ch * 8]);
        }
    }
    cp_commit();
}

__global__ __launch_bounds__(256, 2) void gemm_qk_kernel(int nbase, int isK,
                                                         const float* __restrict__ bias) {
    extern __shared__ __align__(1024) char smem[];
    uint32_t sbase = smem_u32(smem);
    float* qs_s   = reinterpret_cast<float*>(smem + QS_OFF);
    float* bias_s = reinterpret_cast<float*>(smem + BIAS_OFF);
    int tid  = threadIdx.x;
    int warp = tid >> 5, lane = tid & 31;
    int wm = warp & 1, wn = warp >> 1;      // warp grid 2(m) x 4(n)
    int gr = lane >> 2, tg = lane & 3;
    int m0 = blockIdx.x * GBM;
    int n0 = nbase + blockIdx.y * GBN;
    int slot0 = blockIdx.y * 8;

    int j  = lane >> 3;
    int jm = j & 1;
    uint32_t kadd = (uint32_t)(j >> 1) * 16;
    uint32_t xorv = (uint32_t)(lane & 7) << 4;
    int rA[4], rB[2];
#pragma unroll
    for (int mf = 0; mf < 4; mf++) rA[mf] = wm * 64 + mf * 16 + jm * 8 + (lane & 7);
#pragma unroll
    for (int nh = 0; nh < 2; nh++) rB[nh] = wn * 32 + nh * 16 + jm * 8 + (lane & 7);

    float acc[4][4][4];
#pragma unroll
    for (int i = 0; i < 4; i++)
#pragma unroll
        for (int jj = 0; jj < 4; jj++)
#pragma unroll
            for (int q = 0; q < 4; q++) acc[i][jj][q] = 0.f;

    stage_tile(sbase, SM_AOFF(0), SM_BOFF(0), m0, n0, 0, tid);
    for (int i = tid; i < GBM * QSP; i += 256) qs_s[i] = 0.f;
    if (tid < 128) bias_s[tid] = bias[slot0 * 16 + tid];

    for (int kt = 0; kt < NKT; kt++) {
        uint32_t aoff = SM_AOFF(kt & 1);
        uint32_t boff = SM_BOFF(kt & 1);
        if (kt + 1 < NKT) {
            stage_tile(sbase, SM_AOFF((kt + 1) & 1), SM_BOFF((kt + 1) & 1),
                       m0, n0, kt + 1, tid);
            cp_wait<1>();
        } else {
            cp_wait<0>();
        }
        __syncthreads();

        uint32_t abase[4], bbase[2];
#pragma unroll
        for (int mf = 0; mf < 4; mf++) abase[mf] = sbase + aoff + rA[mf] * 128;
#pragma unroll
        for (int nh = 0; nh < 2; nh++) bbase[nh] = sbase + boff + rB[nh] * 128;

        int kend = (kt == 4) ? 32 : 64;
#pragma unroll
        for (int ks = 0; ks < 64; ks += 16) {
            if (ks >= kend) break;
            uint32_t cofs = ((uint32_t)(ks * 2) + kadd) ^ xorv;
            unsigned a[4][4];
#pragma unroll
            for (int mf = 0; mf < 4; mf++)
                ldsm_x4(a[mf][0], a[mf][1], a[mf][2], a[mf][3], abase[mf] + cofs);
            unsigned b[4][2];
#pragma unroll
            for (int nh = 0; nh < 2; nh++) {
                unsigned r0, r1, r2, r3;
                ldsm_x4(r0, r1, r2, r3, bbase[nh] + cofs);
                b[nh * 2][0] = r0; b[nh * 2 + 1][0] = r1;
                b[nh * 2][1] = r2; b[nh * 2 + 1][1] = r3;
            }
#pragma unroll
            for (int mf = 0; mf < 4; mf++)
#pragma unroll
                for (int nf = 0; nf < 4; nf++)
                    mma16816(acc[mf][nf], a[mf], b[nf]);
        }
        __syncthreads();
    }

    int j0 = tg * 2;
    if (!isK) {
        float qp[8][4];
#pragma unroll
        for (int a1 = 0; a1 < 8; a1++)
#pragma unroll
            for (int a2 = 0; a2 < 4; a2++) qp[a1][a2] = 0.f;
#pragma unroll
        for (int p = 0; p < 2; p++) {
            int sl16 = (wn * 2 + p) * 16;
            float b0 = bias_s[sl16 + j0];
            float b1 = bias_s[sl16 + j0 + 1];
            float b2 = bias_s[sl16 + j0 + 8];
            float b3 = bias_s[sl16 + j0 + 9];
#pragma unroll
            for (int mf = 0; mf < 4; mf++) {
#pragma unroll
                for (int h = 0; h < 2; h++) {
                    float v0 = acc[mf][2 * p][2 * h] + b0;
                    float v1 = acc[mf][2 * p][2 * h + 1] + b1;
                    float v2 = acc[mf][2 * p + 1][2 * h] + b2;
                    float v3 = acc[mf][2 * p + 1][2 * h + 1] + b3;
                    float ssq = v0 * v0 + v1 * v1 + v2 * v2 + v3 * v3;
                    ssq += __shfl_xor_sync(0xffffffffu, ssq, 1);
                    ssq += __shfl_xor_sync(0xffffffffu, ssq, 2);
                    float inv = 1.f / fmaxf(sqrtf(ssq), 1e-12f);
                    qp[mf * 2 + h][0] += v0 * inv;
                    qp[mf * 2 + h][1] += v1 * inv;
                    qp[mf * 2 + h][2] += v2 * inv;
                    qp[mf * 2 + h][3] += v3 * inv;
                }
            }
        }
#pragma unroll
        for (int mf = 0; mf < 4; mf++) {
#pragma unroll
            for (int h = 0; h < 2; h++) {
                int row = wm * 64 + mf * 16 + gr + h * 8;
                atomicAdd(&qs_s[row * QSP + j0],     qp[mf * 2 + h][0]);
                atomicAdd(&qs_s[row * QSP + j0 + 1], qp[mf * 2 + h][1]);
                atomicAdd(&qs_s[row * QSP + j0 + 8], qp[mf * 2 + h][2]);
                atomicAdd(&qs_s[row * QSP + j0 + 9], qp[mf * 2 + h][3]);
            }
        }
        __syncthreads();
        for (int idx = tid; idx < GBM * SQG; idx += 256) {
            int row = idx >> 4, col = idx & 15;
            atomicAdd(&g_qsum[(size_t)(m0 + row) * SQG + col], qs_s[row * QSP + col]);
        }
    } else {
#pragma unroll
        for (int mf = 0; mf < 4; mf++) {
#pragma unroll
            for (int h = 0; h < 2; h++) {
                int row = wm * 64 + mf * 16 + gr + h * 8;
                const float* qsr = &g_qsum[(size_t)(m0 + row) * SQG];
                float q0 = qsr[j0], q1 = qsr[j0 + 1], q2 = qsr[j0 + 8], q3 = qsr[j0 + 9];
#pragma unroll
                for (int p = 0; p < 2; p++) {
                    int sl16 = (wn * 2 + p) * 16;
                    float v0 = acc[mf][2 * p][2 * h] + bias_s[sl16 + j0];
                    float v1 = acc[mf][2 * p][2 * h + 1] + bias_s[sl16 + j0 + 1];
                    float v2 = acc[mf][2 * p + 1][2 * h] + bias_s[sl16 + j0 + 8];
                    float v3 = acc[mf][2 * p + 1][2 * h + 1] + bias_s[sl16 + j0 + 9];
                    float ssq = v0 * v0 + v1 * v1 + v2 * v2 + v3 * v3;
                    float dl  = v0 * q0 + v1 * q1 + v2 * q2 + v3 * q3;
                    ssq += __shfl_xor_sync(0xffffffffu, ssq, 1);
                    ssq += __shfl_xor_sync(0xffffffffu, ssq, 2);
                    dl  += __shfl_xor_sync(0xffffffffu, dl, 1);
                    dl  += __shfl_xor_sync(0xffffffffu, dl, 2);
                    float inv = 1.f / fmaxf(sqrtf(ssq), 1e-12f);
                    if (tg == 0)
                        g_attn[(size_t)(m0 + row) * NMEM + slot0 + wn * 2 + p] =
                            dl * inv * (1.f / 64.f);
                }
            }
        }
    }
}

// ---------------- output: out = x + attn @ Wv + bout ----------------
// Block = 128 positions x 32 outputs; thread = 2 consecutive positions x 8 outputs.
// attn held transposed [m][pos] in smem (conflict-free LDS.64 in hot loop);
// packed f32x2 FFMA halves the FMA instruction count; float2 x/out traffic.
#define OP_PITCH 130    // floats per attn_s row (pos dim), even -> float2 aligned

__global__ __launch_bounds__(256) void out_kernel(const float* __restrict__ x,
                                                  const float* __restrict__ bout,
                                                  float* __restrict__ out) {
    __shared__ __align__(16) float attn_s[64][OP_PITCH];   // [m][pos]
    __shared__ __align__(16) float wv_s[64][32];
    int p0 = blockIdx.x * 128;
    int o0 = blockIdx.y * 32;
    int tid = threadIdx.x;
    int pp = tid & 63;          // position pair index (positions 2pp, 2pp+1)
    int oq = tid >> 6;          // 4 groups x 8 outputs

    // load attn [128 pos][64 m] -> transposed smem [m][pos]
#pragma unroll
    for (int i = 0; i < 8; i++) {
        int idx = tid + i * 256;              // 0..2047 float4s
        int pr = idx >> 4;                    // 0..127
        int mc = (idx & 15) * 4;              // 0..60
        float4 a4 = *reinterpret_cast<const float4*>(
            &g_attn[(size_t)(p0 + pr) * NMEM + mc]);
        attn_s[mc][pr]     = a4.x;
        attn_s[mc + 1][pr] = a4.y;
        attn_s[mc + 2][pr] = a4.z;
        attn_s[mc + 3][pr] = a4.w;
    }
    // load Wv slice [64 m][32 o]
#pragma unroll
    for (int i = 0; i < 8; i++) {
        int idx = tid + i * 256;
        int mm = idx >> 5, oo = idx & 31;
        wv_s[mm][oo] = g_Wv[mm * CCH + o0 + oo];
    }
    __syncthreads();

    u64t acc0[4], acc1[4];      // acc0: pos0 (o pairs), acc1: pos1
#pragma unroll
    for (int i2 = 0; i2 < 4; i2++) { acc0[i2] = 0ull; acc1[i2] = 0ull; }

#pragma unroll 8
    for (int m = 0; m < 64; m++) {
        float2 a2 = *reinterpret_cast<const float2*>(&attn_s[m][2 * pp]);
        u64t aa0 = pack2(a2.x, a2.x);
        u64t aa1 = pack2(a2.y, a2.y);
        ulonglong2 w01 = *reinterpret_cast<const ulonglong2*>(&wv_s[m][oq * 8]);
        ulonglong2 w23 = *reinterpret_cast<const ulonglong2*>(&wv_s[m][oq * 8 + 4]);
        acc0[0] = ffma2p(aa0, w01.x, acc0[0]);
        acc0[1] = ffma2p(aa0, w01.y, acc0[1]);
        acc0[2] = ffma2p(aa0, w23.x, acc0[2]);
        acc0[3] = ffma2p(aa0, w23.y, acc0[3]);
        acc1[0] = ffma2p(aa1, w01.x, acc1[0]);
        acc1[1] = ffma2p(aa1, w01.y, acc1[1]);
        acc1[2] = ffma2p(aa1, w23.x, acc1[2]);
        acc1[3] = ffma2p(aa1, w23.y, acc1[3]);
    }

    int p = p0 + 2 * pp;
    int b = p >> 12, s = p & (SS - 1);     // both positions same b (p0 mult of 128)
#pragma unroll
    for (int j2 = 0; j2 < 4; j2++) {
        float lo0, hi0, lo1, hi1;
        unpack2(acc0[j2], lo0, hi0);       // (o=2j, pos0), (o=2j+1, pos0)
        unpack2(acc1[j2], lo1, hi1);       // (o=2j, pos1), (o=2j+1, pos1)
        int o = o0 + oq * 8 + 2 * j2;
        float bo0 = bout[o], bo1 = bout[o + 1];
        size_t gi0 = ((size_t)b * CCH + o) * SS + s;
        float2 xx0 = *reinterpret_cast<const float2*>(&x[gi0]);
        float2 r0; r0.x = xx0.x + lo0 + bo0; r0.y = xx0.y + lo1 + bo0;
        *reinterpret_cast<float2*>(&out[gi0]) = r0;
        size_t gi1 = gi0 + SS;
        float2 xx1 = *reinterpret_cast<const float2*>(&x[gi1]);
        float2 r1; r1.x = xx1.x + hi0 + bo1; r1.y = xx1.y + hi1 + bo1;
        *reinterpret_cast<float2*>(&out[gi1]) = r1;
    }
}

// ---------------- launch ----------------
extern "C" void kernel_launch(void* const* d_in, const int* in_sizes, int n_in,
                              void* d_out, int out_size) {
    const float* x    = (const float*)d_in[0];
    const float* pos  = (const float*)d_in[1];
    const float* wq   = (const float*)d_in[2];
    const float* bq   = (const float*)d_in[3];
    const float* wk   = (const float*)d_in[4];
    const float* bk   = (const float*)d_in[5];
    const float* v    = (const float*)d_in[6];
    const float* wout = (const float*)d_in[7];
    const float* bout = (const float*)d_in[8];
    float* out = (float*)d_out;

    cudaFuncSetAttribute(gemm_qk_kernel,
                         cudaFuncAttributeMaxDynamicSharedMemorySize, SM_TOTAL);
    void* qsum_ptr = nullptr;
    cudaGetSymbolAddress(&qsum_ptr, g_qsum);

    prep_all_kernel<<<PREP_BLOCKS, 256>>>(x, pos, wq, wk, v, wout);
    cudaMemsetAsync(qsum_ptr, 0, (size_t)MP * SQG * sizeof(float), 0);
    gemm_qk_kernel<<<dim3(MP / GBM, 8), 256, SM_TOTAL>>>(0, 0, bq);
    gemm_qk_kernel<<<dim3(MP / GBM, 8), 256, SM_TOTAL>>>(1024, 1, bk);
    out_kernel<<<dim3(MP / 128, CCH / 32), 256>>>(x, bout, out);
}